// round 2
// baseline (speedup 1.0000x reference)
#include <cuda_runtime.h>
#include <cuda_bf16.h>
#include <cstdint>

// out[i,j] = 2*x[i,j] + 5 - (i+j), x: [8192, 8192] fp32
// Pure HBM-streaming kernel. float4 vectorized, 1 float4 per thread.

static constexpr int N_ROWS = 8192;
static constexpr int N_COLS = 8192;
static constexpr int COLS4  = N_COLS / 4;          // 2048 float4 per row
static constexpr long long TOTAL4 = (long long)N_ROWS * COLS4;  // 16,777,216

__global__ __launch_bounds__(256) void fused_map_kernel(
    const float4* __restrict__ in, float4* __restrict__ out)
{
    unsigned int idx = blockIdx.x * 256u + threadIdx.x;   // float4 index, fits in u32 (16M)
    // row = idx / 2048, col4 = idx % 2048  (power of two -> shift/mask)
    unsigned int row  = idx >> 11;
    unsigned int col4 = idx & 2047u;
    // base = 5 - (i + j) for the first lane of this float4
    float base = 5.0f - (float)(row + (col4 << 2));

    float4 v = in[idx];
    float4 o;
    o.x = fmaf(2.0f, v.x, base);
    o.y = fmaf(2.0f, v.y, base - 1.0f);
    o.z = fmaf(2.0f, v.z, base - 2.0f);
    o.w = fmaf(2.0f, v.w, base - 3.0f);
    out[idx] = o;
}

extern "C" void kernel_launch(void* const* d_in, const int* in_sizes, int n_in,
                              void* d_out, int out_size)
{
    const float4* in  = (const float4*)d_in[0];
    float4*       out = (float4*)d_out;
    unsigned int blocks = (unsigned int)(TOTAL4 / 256);   // 65536
    fused_map_kernel<<<blocks, 256>>>(in, out);
}

// round 4
// speedup vs baseline: 1.0016x; 1.0016x over previous
#include <cuda_runtime.h>
#include <cuda_bf16.h>
#include <cstdint>

// out[i,j] = 2*x[i,j] + 5 - (i+j), x: [8192, 8192] fp32
// HBM-streaming kernel: 2 float4 per thread (MLP=2, front-batched loads),
// streaming cache hints (read-once / write-once data).

static constexpr int N_COLS = 8192;
static constexpr int COLS4  = N_COLS / 4;                       // 2048 float4/row
static constexpr unsigned int TOTAL4 = 8192u * COLS4;           // 16,777,216
static constexpr unsigned int HALF4  = TOTAL4 / 2;              // 8,388,608

__device__ __forceinline__ float4 compute(unsigned int idx, float4 v)
{
    unsigned int row  = idx >> 11;          // idx / 2048
    unsigned int col  = (idx & 2047u) << 2; // first scalar column of this float4
    float base = 5.0f - (float)(row + col);
    float4 o;
    o.x = fmaf(2.0f, v.x, base);
    o.y = fmaf(2.0f, v.y, base - 1.0f);
    o.z = fmaf(2.0f, v.z, base - 2.0f);
    o.w = fmaf(2.0f, v.w, base - 3.0f);
    return o;
}

__global__ __launch_bounds__(256) void fused_map_kernel(
    const float4* __restrict__ in, float4* __restrict__ out)
{
    unsigned int t = blockIdx.x * 256u + threadIdx.x;   // 0 .. HALF4-1
    unsigned int i0 = t;
    unsigned int i1 = t + HALF4;

    // Front-batched independent loads (MLP=2), streaming (evict-first) policy.
    float4 v0 = __ldcs(in + i0);
    float4 v1 = __ldcs(in + i1);

    float4 o0 = compute(i0, v0);
    float4 o1 = compute(i1, v1);

    __stcs(out + i0, o0);
    __stcs(out + i1, o1);
}

extern "C" void kernel_launch(void* const* d_in, const int* in_sizes, int n_in,
                              void* d_out, int out_size)
{
    const float4* in  = (const float4*)d_in[0];
    float4*       out = (float4*)d_out;
    unsigned int blocks = HALF4 / 256;   // 32768 blocks
    fused_map_kernel<<<blocks, 256>>>(in, out);
}